// round 3
// baseline (speedup 1.0000x reference)
#include <cuda_runtime.h>

#define DDIM 256
#define KC   512
#define BM   128
#define BN   128
#define BD   8
#define NMAX 131072

// ||e_k||^2 per codebook row (sequential mul+add, emulating XLA sum(e*e))
__device__ float g_esq[KC];
// ||z_n||^2 per input row (sequential mul+add, emulating XLA sum(z*z))
__device__ float g_zsq[NMAX];

__global__ void esq_kernel(const float* __restrict__ cb) {
    int k = blockIdx.x * blockDim.x + threadIdx.x;
    if (k < KC) {
        const float* row = cb + (long long)k * DDIM;
        float acc = 0.f;
        for (int d = 0; d < DDIM; d++) {
            float v = row[d];
            acc = __fadd_rn(acc, __fmul_rn(v, v));   // two roundings, ascending d
        }
        g_esq[k] = acc;
    }
}

__global__ __launch_bounds__(128)
void zsq_kernel(const float* __restrict__ z, int Nrows) {
    __shared__ float tile[128][33];
    const int r0 = blockIdx.x * 128;
    const int t  = threadIdx.x;
    float acc = 0.f;
    for (int d0 = 0; d0 < DDIM; d0 += 32) {
        __syncthreads();
        for (int e = t; e < 128 * 32; e += 128) {
            int r = e >> 5, c = e & 31;
            tile[r][c] = z[(long long)(r0 + r) * DDIM + d0 + c];
        }
        __syncthreads();
        #pragma unroll
        for (int c = 0; c < 32; c++) {
            float v = tile[t][c];
            acc = __fadd_rn(acc, __fmul_rn(v, v));   // strict sequential order
        }
    }
    if (r0 + t < Nrows) g_zsq[r0 + t] = acc;
}

__global__ __launch_bounds__(256, 2)
void vq_main(const float* __restrict__ z, const float* __restrict__ cb,
             float* __restrict__ out, int Nrows, long long qoff4) {
    __shared__ float As[BD][BM];        // z tile, transposed [d][m]
    __shared__ float Bs[BD][BN];        // codebook tile, transposed [d][k]
    __shared__ float red_v[BM][17];     // padded to kill bank conflicts
    __shared__ int   red_i[BM][17];
    __shared__ int   bidx[BM];

    const int tid = threadIdx.x;
    const int tx  = tid & 15;           // code group
    const int ty  = tid >> 4;           // row group
    const int m0  = blockIdx.x * BM;

    const int lrow = tid >> 1;          // 0..127 (tile row for loads)
    const int lseg = (tid & 1) * 4;     // 0 or 4 (float4 segment)

    float zsqv[8];
    #pragma unroll
    for (int i = 0; i < 8; i++) zsqv[i] = g_zsq[m0 + ty * 8 + i];

    float rmin[8];
    int   ridx[8];
    #pragma unroll
    for (int i = 0; i < 8; i++) { rmin[i] = 3.4e38f; ridx[i] = 0; }

    for (int kt = 0; kt < KC; kt += BN) {
        float acc[8][8];
        #pragma unroll
        for (int i = 0; i < 8; i++)
            #pragma unroll
            for (int j = 0; j < 8; j++) acc[i][j] = 0.f;

        for (int d0 = 0; d0 < DDIM; d0 += BD) {
            // prefetch gmem into registers
            float4 av = *reinterpret_cast<const float4*>(
                &z[(long long)(m0 + lrow) * DDIM + d0 + lseg]);
            float4 bv = *reinterpret_cast<const float4*>(
                &cb[(kt + lrow) * DDIM + d0 + lseg]);

            __syncthreads();   // previous iteration's reads done
            As[lseg + 0][lrow] = av.x;
            As[lseg + 1][lrow] = av.y;
            As[lseg + 2][lrow] = av.z;
            As[lseg + 3][lrow] = av.w;
            Bs[lseg + 0][lrow] = bv.x;
            Bs[lseg + 1][lrow] = bv.y;
            Bs[lseg + 2][lrow] = bv.z;
            Bs[lseg + 3][lrow] = bv.w;
            __syncthreads();

            // ascending d, one FMA per step per accumulator — matches the
            // sequential-FMA accumulation of Eigen gebp / cuBLAS SGEMM.
            #pragma unroll
            for (int d = 0; d < BD; d++) {
                float4 a0 = *reinterpret_cast<const float4*>(&As[d][ty * 8]);
                float4 a1 = *reinterpret_cast<const float4*>(&As[d][ty * 8 + 4]);
                float4 b0 = *reinterpret_cast<const float4*>(&Bs[d][tx * 8]);
                float4 b1 = *reinterpret_cast<const float4*>(&Bs[d][tx * 8 + 4]);
                float a[8] = {a0.x, a0.y, a0.z, a0.w, a1.x, a1.y, a1.z, a1.w};
                float b[8] = {b0.x, b0.y, b0.z, b0.w, b1.x, b1.y, b1.z, b1.w};
                #pragma unroll
                for (int i = 0; i < 8; i++)
                    #pragma unroll
                    for (int j = 0; j < 8; j++)
                        acc[i][j] = fmaf(a[i], b[j], acc[i][j]);
            }
        }

        // Emulate reference rounding:
        //   t1 = fl(zsq - 2*g)   (2*g exact => fmaf(-2,g,zsq) is bitwise equal)
        //   d  = fl(t1 + esq)
        // Ascending k + strict '<' => lowest index on exact ties (jnp.argmin).
        #pragma unroll
        for (int j = 0; j < 8; j++) {
            int kidx = kt + tx * 8 + j;
            float esq = g_esq[kidx];
            #pragma unroll
            for (int i = 0; i < 8; i++) {
                float t1   = fmaf(-2.f, acc[i][j], zsqv[i]);
                float cand = __fadd_rn(t1, esq);
                if (cand < rmin[i]) { rmin[i] = cand; ridx[i] = kidx; }
            }
        }
    }

    // cross-thread reduction: 16 threads (tx) share each row
    #pragma unroll
    for (int i = 0; i < 8; i++) {
        red_v[ty * 8 + i][tx] = rmin[i];
        red_i[ty * 8 + i][tx] = ridx[i];
    }
    __syncthreads();
    if (tid < BM) {
        float bv = red_v[tid][0];
        int   bi = red_i[tid][0];
        #pragma unroll
        for (int t = 1; t < 16; t++) {
            float v  = red_v[tid][t];
            int   ix = red_i[tid][t];
            if (v < bv || (v == bv && ix < bi)) { bv = v; bi = ix; }
        }
        bidx[tid] = bi;
    }
    __syncthreads();

    // gather + write both halves: out[0:ND] = fl(z_e + fl(z_q - z_e)) (STE),
    // out[ND:2ND] = z_q
    const float4* cb4 = reinterpret_cast<const float4*>(cb);
    const float4* z4  = reinterpret_cast<const float4*>(z);
    float4* out4 = reinterpret_cast<float4*>(out);
    const long long base = (long long)m0 * (DDIM / 4);
    for (int e = tid; e < BM * (DDIM / 4); e += 256) {
        int r = e >> 6;          // row within tile
        int c = e & 63;          // float4 column
        int k = bidx[r];
        float4 q  = cb4[k * (DDIM / 4) + c];
        float4 ze = z4[base + (long long)r * (DDIM / 4) + c];
        float4 st;
        st.x = __fadd_rn(ze.x, __fsub_rn(q.x, ze.x));
        st.y = __fadd_rn(ze.y, __fsub_rn(q.y, ze.y));
        st.z = __fadd_rn(ze.z, __fsub_rn(q.z, ze.z));
        st.w = __fadd_rn(ze.w, __fsub_rn(q.w, ze.w));
        out4[base + (long long)r * (DDIM / 4) + c] = st;
        if (qoff4 > 0)
            out4[qoff4 + base + (long long)r * (DDIM / 4) + c] = q;
    }
}

extern "C" void kernel_launch(void* const* d_in, const int* in_sizes, int n_in,
                              void* d_out, int out_size) {
    const float* z  = (const float*)d_in[0];
    const float* cb = (const float*)d_in[1];
    int Nrows = in_sizes[0] / DDIM;
    long long ND = (long long)Nrows * DDIM;
    long long qoff4 = ((long long)out_size >= 2 * ND) ? (ND / 4) : 0;

    esq_kernel<<<4, 128>>>(cb);
    zsq_kernel<<<(Nrows + 127) / 128, 128>>>(z, Nrows);
    vq_main<<<Nrows / BM, 256>>>(z, cb, (float*)d_out, Nrows, qoff4);
}

// round 5
// speedup vs baseline: 1.0152x; 1.0152x over previous
#include <cuda_runtime.h>

#define DDIM 256
#define KC   512
#define BM   128
#define BN   256
#define BD   8
#define NMAX 131072

__device__ float g_esq[KC];
__device__ float g_zsq[NMAX];

// Packed f32x2 helpers (Blackwell sm_103a). Each lane is an independent IEEE
// fp32 op — bitwise identical to scalar fmaf per lane.
#define FMA2(acc, a, b) \
    asm("fma.rn.f32x2 %0, %1, %2, %0;" : "+l"(acc) : "l"(a), "l"(b))
#define PACK_DUP2(dst, f) do { unsigned _u = __float_as_uint(f); \
    asm("mov.b64 %0, {%1, %1};" : "=l"(dst) : "r"(_u)); } while (0)
#define UNPACK2(lo, hi, v) do { unsigned _a, _b; \
    asm("mov.b64 {%0, %1}, %2;" : "=r"(_a), "=r"(_b) : "l"(v)); \
    lo = __uint_as_float(_a); hi = __uint_as_float(_b); } while (0)

// Strict-sequential sum(x*x) per row: fl(acc + fl(v*v)), ascending d.
// Emulates XLA's mul-then-reduce bitwise (proven in R3).
__global__ __launch_bounds__(128)
void rowsq_kernel(const float* __restrict__ src, int nrows, int which) {
    __shared__ float tile[128][33];
    const int r0 = blockIdx.x * 128;
    const int t  = threadIdx.x;
    float acc = 0.f;
    for (int d0 = 0; d0 < DDIM; d0 += 32) {
        __syncthreads();
        for (int e = t; e < 128 * 32; e += 128) {
            int r = e >> 5, c = e & 31;
            if (r0 + r < nrows)
                tile[r][c] = src[(long long)(r0 + r) * DDIM + d0 + c];
        }
        __syncthreads();
        #pragma unroll
        for (int c = 0; c < 32; c++) {
            float v = tile[t][c];
            acc = __fadd_rn(acc, __fmul_rn(v, v));
        }
    }
    if (r0 + t < nrows) {
        if (which) g_zsq[r0 + t] = acc;
        else       g_esq[r0 + t] = acc;
    }
}

__global__ __launch_bounds__(256, 1)
void vq_main(const float* __restrict__ z, const float* __restrict__ cb,
             float* __restrict__ out, long long qoff4) {
    __shared__ __align__(16) float As[BD][BM];   // z tile [d][m]
    __shared__ __align__(16) float Bs[BD][BN];   // codebook tile [d][k]
    __shared__ float red_v[BM][33];
    __shared__ int   red_i[BM][33];
    __shared__ int   bidx[BM];

    const int tid = threadIdx.x;
    const int tx  = tid & 31;          // code group (warp lanes)
    const int ty  = tid >> 5;          // warp id = row group, 0..7
    const int m0  = blockIdx.x * BM;

    float rmin[16];
    int   ridx[16];
    #pragma unroll
    for (int i = 0; i < 16; i++) { rmin[i] = 3.4e38f; ridx[i] = 0; }

    for (int kt = 0; kt < KC; kt += BN) {
        unsigned long long acc[8][8];   // f32x2 pairs: rows (2ip,2ip+1) x code jp
        #pragma unroll
        for (int ip = 0; ip < 8; ip++)
            #pragma unroll
            for (int jp = 0; jp < 8; jp++) acc[ip][jp] = 0ull;

        // prefetch stage 0 into registers
        float4 av0, av1, bv0, bv1;
        if (tid < BM) {
            const float* zp = z + (long long)(m0 + tid) * DDIM;
            av0 = *reinterpret_cast<const float4*>(zp);
            av1 = *reinterpret_cast<const float4*>(zp + 4);
        }
        {
            const float* bp = cb + (long long)(kt + tid) * DDIM;
            bv0 = *reinterpret_cast<const float4*>(bp);
            bv1 = *reinterpret_cast<const float4*>(bp + 4);
        }

        for (int d0 = 0; d0 < DDIM; d0 += BD) {
            __syncthreads();   // previous stage's smem reads done
            if (tid < BM) {
                As[0][tid] = av0.x; As[1][tid] = av0.y;
                As[2][tid] = av0.z; As[3][tid] = av0.w;
                As[4][tid] = av1.x; As[5][tid] = av1.y;
                As[6][tid] = av1.z; As[7][tid] = av1.w;
            }
            Bs[0][tid] = bv0.x; Bs[1][tid] = bv0.y;
            Bs[2][tid] = bv0.z; Bs[3][tid] = bv0.w;
            Bs[4][tid] = bv1.x; Bs[5][tid] = bv1.y;
            Bs[6][tid] = bv1.z; Bs[7][tid] = bv1.w;
            __syncthreads();

            // issue next stage's gmem loads now; latency hides under compute
            if (d0 + BD < DDIM) {
                if (tid < BM) {
                    const float* zp = z + (long long)(m0 + tid) * DDIM + d0 + BD;
                    av0 = *reinterpret_cast<const float4*>(zp);
                    av1 = *reinterpret_cast<const float4*>(zp + 4);
                }
                const float* bp = cb + (long long)(kt + tid) * DDIM + d0 + BD;
                bv0 = *reinterpret_cast<const float4*>(bp);
                bv1 = *reinterpret_cast<const float4*>(bp + 4);
            }

            // 8 depths; ascending d, one FMA per accumulator per depth —
            // bitwise-identical accumulation order to the R3 scalar kernel.
            #pragma unroll
            for (int d = 0; d < BD; d++) {
                ulonglong2 aA = *reinterpret_cast<const ulonglong2*>(&As[d][ty * 16 + 0]);
                ulonglong2 aB = *reinterpret_cast<const ulonglong2*>(&As[d][ty * 16 + 4]);
                ulonglong2 aC = *reinterpret_cast<const ulonglong2*>(&As[d][ty * 16 + 8]);
                ulonglong2 aD = *reinterpret_cast<const ulonglong2*>(&As[d][ty * 16 + 12]);
                unsigned long long a2[8] = {aA.x, aA.y, aB.x, aB.y,
                                            aC.x, aC.y, aD.x, aD.y};
                float4 b0 = *reinterpret_cast<const float4*>(&Bs[d][tx * 8]);
                float4 b1 = *reinterpret_cast<const float4*>(&Bs[d][tx * 8 + 4]);
                float bsv[8] = {b0.x, b0.y, b0.z, b0.w, b1.x, b1.y, b1.z, b1.w};
                unsigned long long bb[8];
                #pragma unroll
                for (int jp = 0; jp < 8; jp++) PACK_DUP2(bb[jp], bsv[jp]);
                #pragma unroll
                for (int ip = 0; ip < 8; ip++)
                    #pragma unroll
                    for (int jp = 0; jp < 8; jp++)
                        FMA2(acc[ip][jp], a2[ip], bb[jp]);
            }
        }

        // Epilogue: d = fl(fl(zsq - 2*g) + esq); ascending k + strict '<'
        // keeps lowest index on exact ties (jnp.argmin semantics).
        #pragma unroll
        for (int jp = 0; jp < 8; jp++) {
            int kidx = kt + tx * 8 + jp;
            float esq = g_esq[kidx];
            #pragma unroll
            for (int ip = 0; ip < 8; ip++) {
                float glo, ghi;
                UNPACK2(glo, ghi, acc[ip][jp]);
                float z0 = g_zsq[m0 + ty * 16 + 2 * ip];
                float z1 = g_zsq[m0 + ty * 16 + 2 * ip + 1];
                float c0 = __fadd_rn(fmaf(-2.f, glo, z0), esq);
                float c1 = __fadd_rn(fmaf(-2.f, ghi, z1), esq);
                if (c0 < rmin[2 * ip])     { rmin[2 * ip]     = c0; ridx[2 * ip]     = kidx; }
                if (c1 < rmin[2 * ip + 1]) { rmin[2 * ip + 1] = c1; ridx[2 * ip + 1] = kidx; }
            }
        }
    }

    // cross-thread reduction: 32 lanes (tx) share each row
    #pragma unroll
    for (int i = 0; i < 16; i++) {
        red_v[ty * 16 + i][tx] = rmin[i];
        red_i[ty * 16 + i][tx] = ridx[i];
    }
    __syncthreads();
    if (tid < BM) {
        float bv = red_v[tid][0];
        int   bi = red_i[tid][0];
        #pragma unroll
        for (int t = 1; t < 32; t++) {
            float v  = red_v[tid][t];
            int   ix = red_i[tid][t];
            if (v < bv || (v == bv && ix < bi)) { bv = v; bi = ix; }
        }
        bidx[tid] = bi;
    }
    __syncthreads();

    // gather + write both halves: out[0:ND] = fl(z_e + fl(z_q - z_e)) (STE),
    // out[ND:2ND] = z_q
    const float4* cb4 = reinterpret_cast<const float4*>(cb);
    const float4* z4  = reinterpret_cast<const float4*>(z);
    float4* out4 = reinterpret_cast<float4*>(out);
    const long long base = (long long)m0 * (DDIM / 4);
    for (int e = tid; e < BM * (DDIM / 4); e += 256) {
        int r = e >> 6;
        int c = e & 63;
        int k = bidx[r];
        float4 q  = cb4[k * (DDIM / 4) + c];
        float4 ze = z4[base + (long long)r * (DDIM / 4) + c];
        float4 st;
        st.x = __fadd_rn(ze.x, __fsub_rn(q.x, ze.x));
        st.y = __fadd_rn(ze.y, __fsub_rn(q.y, ze.y));
        st.z = __fadd_rn(ze.z, __fsub_rn(q.z, ze.z));
        st.w = __fadd_rn(ze.w, __fsub_rn(q.w, ze.w));
        out4[base + (long long)r * (DDIM / 4) + c] = st;
        if (qoff4 > 0)
            out4[qoff4 + base + (long long)r * (DDIM / 4) + c] = q;
    }
}

extern "C" void kernel_launch(void* const* d_in, const int* in_sizes, int n_in,
                              void* d_out, int out_size) {
    const float* z  = (const float*)d_in[0];
    const float* cb = (const float*)d_in[1];
    int Nrows = in_sizes[0] / DDIM;
    long long ND = (long long)Nrows * DDIM;
    long long qoff4 = ((long long)out_size >= 2 * ND) ? (ND / 4) : 0;

    rowsq_kernel<<<(KC + 127) / 128, 128>>>(cb, KC, 0);
    rowsq_kernel<<<(Nrows + 127) / 128, 128>>>(z, Nrows, 1);
    vq_main<<<Nrows / BM, 256>>>(z, cb, (float*)d_out, qoff4);
}